// round 5
// baseline (speedup 1.0000x reference)
#include <cuda_runtime.h>

// Problem constants
#define Nn 8
#define Cc 256
#define Tt 1024
#define Vv 25
#define Hh 8
#define Dd 64
#define HC 512   // Hh * Dd

// Precomputed small tensors (batch/time independent)
__device__ float g_q[HC * Vv];
__device__ float g_k[HC * Vv];
__device__ float g_attn[Hh * Vv * Vv];

// ---------------- helpers ----------------
__device__ __forceinline__ unsigned f2tf(float x) {
    unsigned r; asm("cvt.rna.tf32.f32 %0, %1;" : "=r"(r) : "f"(x)); return r;
}
__device__ __forceinline__ void mma8(float* c, unsigned a0, unsigned a1, unsigned a2,
                                     unsigned a3, unsigned b0, unsigned b1) {
    asm("mma.sync.aligned.m16n8k8.row.col.f32.tf32.tf32.f32 "
        "{%0,%1,%2,%3}, {%4,%5,%6,%7}, {%8,%9}, {%0,%1,%2,%3};"
        : "+f"(c[0]), "+f"(c[1]), "+f"(c[2]), "+f"(c[3])
        : "r"(a0), "r"(a1), "r"(a2), "r"(a3), "r"(b0), "r"(b1));
}
__device__ __forceinline__ void cpasync16(float* dst, const float* src) {
    unsigned d = (unsigned)__cvta_generic_to_shared(dst);
    asm volatile("cp.async.cg.shared.global [%0], [%1], 16;" :: "r"(d), "l"(src));
}
__device__ __forceinline__ unsigned fbits(float x) { return __float_as_uint(x); }
__device__ __forceinline__ float ubits(unsigned x) { return __uint_as_float(x); }

// ---------------------------------------------------------------------------
// Kernel 1: q = Wq @ tf + bq, k = Wk @ tf + bk
// ---------------------------------------------------------------------------
__global__ void qk_kernel(const float* __restrict__ tf,
                          const float* __restrict__ Wq, const float* __restrict__ bq,
                          const float* __restrict__ Wk, const float* __restrict__ bk) {
    extern __shared__ float tf_s[];
    for (int idx = threadIdx.x; idx < HC * Vv; idx += blockDim.x) tf_s[idx] = tf[idx];
    __syncthreads();

    int g = blockIdx.x * blockDim.x + threadIdx.x;
    int which = (g >= HC * Vv) ? 1 : 0;
    int r = which ? (g - HC * Vv) : g;
    int hc = r / Vv;
    int u = r - hc * Vv;
    const float* wrow = (which ? Wk : Wq) + hc * 512;
    float acc = which ? bk[hc] : bq[hc];
#pragma unroll 8
    for (int i = 0; i < 512; i++) acc += wrow[i] * tf_s[i * Vv + u];
    if (which) g_k[r] = acc; else g_q[r] = acc;
}

// ---------------------------------------------------------------------------
// Kernel 2: energy + softmax -> g_attn
// ---------------------------------------------------------------------------
__global__ void attn_kernel() {
    extern __shared__ float s[];
    float* q_s = s;
    float* k_s = s + HC * Vv;
    for (int idx = threadIdx.x; idx < HC * Vv; idx += blockDim.x) {
        q_s[idx] = g_q[idx];
        k_s[idx] = g_k[idx];
    }
    __syncthreads();

    int r = threadIdx.x;
    if (r < Hh * Vv) {
        int h = r / Vv;
        int u = r - h * Vv;
        float e[Vv];
#pragma unroll
        for (int j = 0; j < Vv; j++) e[j] = 0.f;
        const float* qb = q_s + h * Dd * Vv;
        const float* kb = k_s + h * Dd * Vv;
        for (int c = 0; c < Dd; c++) {
            float qv = qb[c * Vv + u];
#pragma unroll
            for (int j = 0; j < Vv; j++) e[j] += qv * kb[c * Vv + j];
        }
        float m = -1e30f;
#pragma unroll
        for (int j = 0; j < Vv; j++) { e[j] *= 0.125f; m = fmaxf(m, e[j]); }
        float ssum = 0.f;
#pragma unroll
        for (int j = 0; j < Vv; j++) { e[j] = expf(e[j] - m); ssum += e[j]; }
        float inv = 1.f / ssum;
        float* arow = g_attn + (h * Vv + u) * Vv;
#pragma unroll
        for (int j = 0; j < Vv; j++) arow[j] = e[j] * inv;
    }
}

// ---------------------------------------------------------------------------
// Kernel 3: fully-fused tf32 tensor-core kernel.
// One block = 256 threads = 8 warps, handles columns [ct*100, ct*100+100) of
// batch n (100 cols = 4 t's x 25 v).
//
// SMEM float offsets:
//   F_s  [64][104]  @0      (fp32 F K-chunk; b-operand of V-stage)
//   Wv_s [64][68]   @6656   (tf32)
//   V_s  [64][132]  @11008  (tf32, layout [c][tl*32+u], u>=25 zero)
//   Z_s  [104][68]  @19456  (tf32, col-major [col][c])
//   AT_s [8][32][36]@26528  (tf32, attn^T padded: [h][v][u])
//   Wo_s [256][68]  @35744  (fp32 raw; cvt at a-frag load)
//   bv_s 64 @53152, bo_s 256 @53216   -> total 53472 floats = 213888 B
// ---------------------------------------------------------------------------
#define FS_OFF  0
#define WVS_OFF 6656
#define VS_OFF  11008
#define ZS_OFF  19456
#define ATS_OFF 26528
#define WOS_OFF 35744
#define BVS_OFF 53152
#define BOS_OFF 53216
#define SMEM_FLOATS 53472

__global__ void __launch_bounds__(256, 1)
main_kernel(const float* __restrict__ f, const float* __restrict__ Wv,
            const float* __restrict__ bv, const float* __restrict__ Wo,
            const float* __restrict__ bo, float* __restrict__ out) {
    extern __shared__ float s[];
    float* F_s  = s + FS_OFF;
    float* Wv_s = s + WVS_OFF;
    float* V_s  = s + VS_OFF;
    float* Z_s  = s + ZS_OFF;
    float* AT_s = s + ATS_OFF;
    float* Wo_s = s + WOS_OFF;
    float* bv_s = s + BVS_OFF;
    float* bo_s = s + BOS_OFF;

    const int tid  = threadIdx.x;
    const int lane = tid & 31;
    const int wid  = tid >> 5;
    const int bI   = blockIdx.x;
    const int n    = bI >> 8;
    const int ct   = bI & 255;

    // ---- init: zero padded regions, load biases ----
    for (int i = tid; i < 8448; i += 256) V_s[i] = 0.f;
    for (int i = tid; i < 7072; i += 256) Z_s[i] = 0.f;
    for (int i = tid; i < 9216; i += 256) AT_s[i] = 0.f;
    if (tid < 64) bv_s[tid] = bv[tid];
    bo_s[tid] = bo[tid];
    {   // F pad cols 100..103
        int r = tid >> 2, c = tid & 3;
        F_s[r * 104 + 100 + c] = 0.f;
    }
    __syncthreads();
    // attn^T (tf32) fill: AT[h][v][u] = attn[h][u][v]
    for (int idx = tid; idx < Hh * Vv * Vv; idx += 256) {
        int h = idx / 625, rem = idx - h * 625;
        int u = rem / 25, v = rem - u * 25;
        AT_s[h * 1152 + v * 36 + u] = ubits(f2tf(g_attn[idx]));
    }

    // ================= Stage V: V = Wv @ F + bv (tf32 mma) =================
    const int v_mt  = wid & 3;          // m-tile (16 rows each, M=64)
    const int v_nt0 = (wid >> 2) ? 7 : 0;
    float vacc[7][4];
#pragma unroll
    for (int i = 0; i < 7; i++)
#pragma unroll
        for (int j = 0; j < 4; j++) vacc[i][j] = 0.f;

    const float4* f4base = (const float4*)(f + (size_t)n * 6553600 + (size_t)ct * 100);

    for (int kc = 0; kc < 4; kc++) {
        // load F chunk rows kc*64..kc*64+63, 100 floats each (25 float4)
        for (int idx4 = tid; idx4 < 1600; idx4 += 256) {
            int r = idx4 / 25, q = idx4 - r * 25;
            float4 v4 = f4base[((size_t)(kc * 64 + r) * 25600) / 4 + q];
            *(float4*)(F_s + r * 104 + q * 4) = v4;
        }
        // load Wv chunk (tf32-rounded)
        for (int idx4 = tid; idx4 < 1024; idx4 += 256) {
            int r = idx4 >> 4, j = idx4 & 15;
            float4 v4 = *(const float4*)(Wv + r * 256 + kc * 64 + j * 4);
            float4 o4;
            o4.x = ubits(f2tf(v4.x)); o4.y = ubits(f2tf(v4.y));
            o4.z = ubits(f2tf(v4.z)); o4.w = ubits(f2tf(v4.w));
            *(float4*)(Wv_s + r * 68 + j * 4) = o4;
        }
        __syncthreads();
#pragma unroll
        for (int ks = 0; ks < 8; ks++) {
            int k = ks * 8;
            const float* wvb = Wv_s + (v_mt * 16 + (lane >> 2)) * 68 + k + (lane & 3);
            unsigned a0 = fbits(wvb[0]),      a1 = fbits(wvb[8 * 68]);
            unsigned a2 = fbits(wvb[4]),      a3 = fbits(wvb[8 * 68 + 4]);
#pragma unroll
            for (int i = 0; i < 7; i++) {
                int nt = v_nt0 + i;
                const float* fb = F_s + (k + (lane & 3)) * 104 + nt * 8 + (lane >> 2);
                unsigned b0 = f2tf(fb[0]), b1 = f2tf(fb[4 * 104]);
                mma8(vacc[i], a0, a1, a2, a3, b0, b1);
            }
        }
        __syncthreads();
    }
    // V epilogue -> V_s (tf32, remapped [c][tl*32+u])
    {
        int r0 = v_mt * 16 + (lane >> 2);
        float bv0 = bv_s[r0], bv1 = bv_s[r0 + 8];
#pragma unroll
        for (int i = 0; i < 7; i++) {
            int nt = v_nt0 + i;
            int col0 = nt * 8 + (lane & 3) * 2;
            if (col0 < 100) {
                int tl = col0 / 25, u = col0 - tl * 25;
                V_s[r0 * 132 + tl * 32 + u]       = ubits(f2tf(vacc[i][0] + bv0));
                V_s[(r0 + 8) * 132 + tl * 32 + u] = ubits(f2tf(vacc[i][2] + bv1));
            }
            int c1 = col0 + 1;
            if (c1 < 100) {
                int tl = c1 / 25, u = c1 - tl * 25;
                V_s[r0 * 132 + tl * 32 + u]       = ubits(f2tf(vacc[i][1] + bv0));
                V_s[(r0 + 8) * 132 + tl * 32 + u] = ubits(f2tf(vacc[i][3] + bv1));
            }
        }
    }
    __syncthreads();

    // ================= Head loop: Z-gen + main mma =================
    const int z_tl = wid & 3;     // t-local for Z-gen
    const int z_mh = wid >> 2;    // c-half for Z-gen
    float macc[2][13][4];
#pragma unroll
    for (int mi = 0; mi < 2; mi++)
#pragma unroll
        for (int nt = 0; nt < 13; nt++)
#pragma unroll
            for (int j = 0; j < 4; j++) macc[mi][nt][j] = 0.f;

    for (int h = 0; h < 8; h++) {
        __syncthreads();  // prior readers of Z_s / Wo_s done

        // prefetch Wo chunk [256][64] via cp.async (raw fp32)
        for (int idx4 = tid; idx4 < 4096; idx4 += 256) {
            int o = idx4 >> 4, j = idx4 & 15;
            cpasync16(Wo_s + o * 68 + j * 4, Wo + o * 512 + h * 64 + j * 4);
        }
        asm volatile("cp.async.commit_group;");

        // ---- Z-gen mma: Z_t[64c, 25v] = V_t[64c, 25u] @ attn_h[25u, 25v] ----
        float zacc[2][4][4];
#pragma unroll
        for (int mi = 0; mi < 2; mi++)
#pragma unroll
            for (int nt = 0; nt < 4; nt++)
#pragma unroll
                for (int j = 0; j < 4; j++) zacc[mi][nt][j] = 0.f;

#pragma unroll
        for (int ks = 0; ks < 4; ks++) {
            int k = ks * 8;
#pragma unroll
            for (int mi = 0; mi < 2; mi++) {
                const float* vb = V_s + (z_mh * 32 + mi * 16 + (lane >> 2)) * 132
                                  + z_tl * 32 + k + (lane & 3);
                unsigned a0 = fbits(vb[0]),  a1 = fbits(vb[8 * 132]);
                unsigned a2 = fbits(vb[4]),  a3 = fbits(vb[8 * 132 + 4]);
#pragma unroll
                for (int nt = 0; nt < 4; nt++) {
                    const float* ab = AT_s + h * 1152 + (nt * 8 + (lane >> 2)) * 36
                                      + k + (lane & 3);
                    mma8(zacc[mi][nt], a0, a1, a2, a3, fbits(ab[0]), fbits(ab[4]));
                }
            }
        }
        // store Z (tf32, col-major [col][c])
#pragma unroll
        for (int mi = 0; mi < 2; mi++) {
            int r0 = z_mh * 32 + mi * 16 + (lane >> 2);
#pragma unroll
            for (int nt = 0; nt < 4; nt++) {
                int v0 = nt * 8 + (lane & 3) * 2;
                if (v0 < 25) {
                    int zc = (z_tl * 25 + v0) * 68;
                    Z_s[zc + r0]     = ubits(f2tf(zacc[mi][nt][0]));
                    Z_s[zc + r0 + 8] = ubits(f2tf(zacc[mi][nt][2]));
                }
                if (v0 + 1 < 25) {
                    int zc = (z_tl * 25 + v0 + 1) * 68;
                    Z_s[zc + r0]     = ubits(f2tf(zacc[mi][nt][1]));
                    Z_s[zc + r0 + 8] = ubits(f2tf(zacc[mi][nt][3]));
                }
            }
        }
        asm volatile("cp.async.wait_group 0;" ::: "memory");
        __syncthreads();  // Wo_s and Z_s ready

        // ---- main mma: acc[256,104] += Wo_h[256,64] @ Z[64,104] ----
#pragma unroll
        for (int ks = 0; ks < 8; ks++) {
            int k = ks * 8;
            unsigned bz[13][2];
#pragma unroll
            for (int nt = 0; nt < 13; nt++) {
                const float* zb = Z_s + (nt * 8 + (lane >> 2)) * 68 + k + (lane & 3);
                bz[nt][0] = fbits(zb[0]);
                bz[nt][1] = fbits(zb[4]);
            }
#pragma unroll
            for (int mi = 0; mi < 2; mi++) {
                const float* wb = Wo_s + (wid * 32 + mi * 16 + (lane >> 2)) * 68
                                  + k + (lane & 3);
                unsigned a0 = f2tf(wb[0]), a1 = f2tf(wb[8 * 68]);
                unsigned a2 = f2tf(wb[4]), a3 = f2tf(wb[8 * 68 + 4]);
#pragma unroll
                for (int nt = 0; nt < 13; nt++)
                    mma8(macc[mi][nt], a0, a1, a2, a3, bz[nt][0], bz[nt][1]);
            }
        }
    }

    // ================= Epilogue: + bo + residual f =================
    {
        const size_t base = (size_t)n * 6553600 + (size_t)ct * 100;
#pragma unroll
        for (int mi = 0; mi < 2; mi++) {
            int r0 = wid * 32 + mi * 16 + (lane >> 2);
            float bo0 = bo_s[r0], bo1 = bo_s[r0 + 8];
#pragma unroll
            for (int nt = 0; nt < 13; nt++) {
                int col0 = nt * 8 + (lane & 3) * 2;
                if (col0 < 100) {
                    size_t a0 = base + (size_t)r0 * 25600 + col0;
                    size_t a2 = base + (size_t)(r0 + 8) * 25600 + col0;
                    out[a0] = macc[mi][nt][0] + bo0 + __ldg(f + a0);
                    out[a2] = macc[mi][nt][2] + bo1 + __ldg(f + a2);
                }
                int c1 = col0 + 1;
                if (c1 < 100) {
                    size_t a1 = base + (size_t)r0 * 25600 + c1;
                    size_t a3 = base + (size_t)(r0 + 8) * 25600 + c1;
                    out[a1] = macc[mi][nt][1] + bo0 + __ldg(f + a1);
                    out[a3] = macc[mi][nt][3] + bo1 + __ldg(f + a3);
                }
            }
        }
    }
}

// ---------------------------------------------------------------------------
extern "C" void kernel_launch(void* const* d_in, const int* in_sizes, int n_in,
                              void* d_out, int out_size) {
    const float* feature = (const float*)d_in[0];
    const float* tf      = (const float*)d_in[1];
    const float* Wq      = (const float*)d_in[2];
    const float* bq      = (const float*)d_in[3];
    const float* Wk      = (const float*)d_in[4];
    const float* bk      = (const float*)d_in[5];
    const float* Wv      = (const float*)d_in[6];
    const float* bv      = (const float*)d_in[7];
    const float* Wo      = (const float*)d_in[8];
    const float* bo      = (const float*)d_in[9];
    float* out = (float*)d_out;

    const size_t qk_smem   = (size_t)HC * Vv * sizeof(float);
    const size_t attn_smem = (size_t)2 * HC * Vv * sizeof(float);
    const size_t main_smem = (size_t)SMEM_FLOATS * sizeof(float);  // 213888 B

    cudaFuncSetAttribute((const void*)qk_kernel,
                         cudaFuncAttributeMaxDynamicSharedMemorySize, (int)qk_smem);
    cudaFuncSetAttribute((const void*)attn_kernel,
                         cudaFuncAttributeMaxDynamicSharedMemorySize, (int)attn_smem);
    cudaFuncSetAttribute((const void*)main_kernel,
                         cudaFuncAttributeMaxDynamicSharedMemorySize, (int)main_smem);

    qk_kernel<<<100, 256, qk_smem>>>(tf, Wq, bq, Wk, bk);
    attn_kernel<<<1, 256, attn_smem>>>();
    main_kernel<<<Nn * 256, 256, main_smem>>>(feature, Wv, bv, Wo, bo, out);
}

// round 8
// speedup vs baseline: 1.4274x; 1.4274x over previous
#include <cuda_runtime.h>
#include <cuda_bf16.h>

// Problem constants
#define Nn 8
#define Cc 256
#define Tt 1024
#define Vv 25
#define Hh 8
#define Dd 64
#define HC 512

typedef unsigned int u32;
typedef unsigned long long u64;
typedef __nv_bfloat16 bf16;

// Precomputed globals
__device__ float g_q[HC * Vv];
__device__ float g_k[HC * Vv];
__device__ float g_attn[Hh * Vv * Vv];
__device__ bf16 g_Wo_b[256 * 512];

// ---------------- helpers ----------------
__device__ __forceinline__ void mma16(float* c, u32 a0, u32 a1, u32 a2, u32 a3,
                                      u32 b0, u32 b1) {
    asm("mma.sync.aligned.m16n8k16.row.col.f32.bf16.bf16.f32 "
        "{%0,%1,%2,%3}, {%4,%5,%6,%7}, {%8,%9}, {%0,%1,%2,%3};"
        : "+f"(c[0]), "+f"(c[1]), "+f"(c[2]), "+f"(c[3])
        : "r"(a0), "r"(a1), "r"(a2), "r"(a3), "r"(b0), "r"(b1));
}
__device__ __forceinline__ void cpasync16(u32 dst_smem, const void* src) {
    asm volatile("cp.async.cg.shared.global [%0], [%1], 16;" :: "r"(dst_smem), "l"(src));
}
__device__ __forceinline__ u32 smem_u32(const void* p) {
    return (u32)__cvta_generic_to_shared(p);
}
__device__ __forceinline__ u32 ld32(const bf16* p) { return *(const u32*)p; }

// SMEM byte offsets (main kernel)
#define OFF_BV   0        // 64 fp32
#define OFF_BO   256      // 256 fp32
#define OFF_AT   1280     // bf16 [8][32][40]      = 20480 B
#define OFF_VS   21760    // bf16 [64][136]        = 17408 B
#define OFF_ZS   39168    // bf16 [104][72]        = 14976 B
#define OFF_WO   54144    // bf16 2 x [256][72]    = 73728 B (union w/ FT+Wv below)
#define OFF_FT   54144    // bf16 [104][72]        = 14976 B (V-stage only)
#define OFF_WVS  69120    // bf16 [64][72]         =  9216 B (V-stage only)
#define WO_BUF   36864
#define SMEM_MAIN 127872

// ---------------------------------------------------------------------------
// Kernel 1: q/k GEMV, warp-per-5-outputs, coalesced W rows. 640 blocks x 8 warps.
// ---------------------------------------------------------------------------
__global__ void qk_kernel(const float* __restrict__ tf,
                          const float* __restrict__ Wq, const float* __restrict__ bq,
                          const float* __restrict__ Wk, const float* __restrict__ bk) {
    extern __shared__ float tf_s[];
    for (int idx = threadIdx.x; idx < HC * Vv; idx += blockDim.x) tf_s[idx] = tf[idx];
    __syncthreads();

    int wid = threadIdx.x >> 5, lane = threadIdx.x & 31;
    int gw = blockIdx.x * 8 + wid;
    int which = gw >= 2560;
    int rowid = gw - which * 2560;
    int hc = rowid / 5;
    int u0 = (rowid - hc * 5) * 5;
    const float* wrow = (which ? Wk : Wq) + hc * 512;

    float acc[5] = {0, 0, 0, 0, 0};
#pragma unroll
    for (int i = 0; i < 16; i++) {
        int k = i * 32 + lane;
        float w = wrow[k];
        const float* tb = tf_s + k * Vv + u0;
#pragma unroll
        for (int j = 0; j < 5; j++) acc[j] += w * tb[j];
    }
#pragma unroll
    for (int j = 0; j < 5; j++)
#pragma unroll
        for (int off = 16; off; off >>= 1)
            acc[j] += __shfl_xor_sync(0xFFFFFFFF, acc[j], off);

    if (lane == 0) {
        float b = (which ? bk : bq)[hc];
        float* dst = (which ? g_k : g_q) + hc * Vv + u0;
#pragma unroll
        for (int j = 0; j < 5; j++) dst[j] = acc[j] + b;
    }
}

// ---------------------------------------------------------------------------
// Kernel 2: energy + softmax -> g_attn
// ---------------------------------------------------------------------------
__global__ void attn_kernel() {
    extern __shared__ float s[];
    float* q_s = s;
    float* k_s = s + HC * Vv;
    for (int idx = threadIdx.x; idx < HC * Vv; idx += blockDim.x) {
        q_s[idx] = g_q[idx];
        k_s[idx] = g_k[idx];
    }
    __syncthreads();

    int r = threadIdx.x;
    if (r < Hh * Vv) {
        int h = r / Vv;
        int u = r - h * Vv;
        float e[Vv];
#pragma unroll
        for (int j = 0; j < Vv; j++) e[j] = 0.f;
        const float* qb = q_s + h * Dd * Vv;
        const float* kb = k_s + h * Dd * Vv;
        for (int c = 0; c < Dd; c++) {
            float qv = qb[c * Vv + u];
#pragma unroll
            for (int j = 0; j < Vv; j++) e[j] += qv * kb[c * Vv + j];
        }
        float m = -1e30f;
#pragma unroll
        for (int j = 0; j < Vv; j++) { e[j] *= 0.125f; m = fmaxf(m, e[j]); }
        float ssum = 0.f;
#pragma unroll
        for (int j = 0; j < Vv; j++) { e[j] = expf(e[j] - m); ssum += e[j]; }
        float inv = 1.f / ssum;
        float* arow = g_attn + (h * Vv + u) * Vv;
#pragma unroll
        for (int j = 0; j < Vv; j++) arow[j] = e[j] * inv;
    }
}

// ---------------------------------------------------------------------------
// Kernel 2b: Wo -> bf16 prep
// ---------------------------------------------------------------------------
__global__ void wo_prep(const float* __restrict__ Wo) {
    int i = blockIdx.x * 256 + threadIdx.x;
    g_Wo_b[i] = __float2bfloat16(Wo[i]);
}

// ---------------------------------------------------------------------------
// Kernel 3 (main): one block per (n, 100 cols = 4t x 25v). All-bf16 mma.sync.
// ---------------------------------------------------------------------------
__global__ void __launch_bounds__(256, 1)
main_kernel(const float* __restrict__ f, const float* __restrict__ Wv,
            const float* __restrict__ bv, const float* __restrict__ bo,
            float* __restrict__ out) {
    extern __shared__ char smem_c[];
    float* bv_s = (float*)(smem_c + OFF_BV);
    float* bo_s = (float*)(smem_c + OFF_BO);
    bf16* ATp  = (bf16*)(smem_c + OFF_AT);
    bf16* Vp   = (bf16*)(smem_c + OFF_VS);
    bf16* Zp   = (bf16*)(smem_c + OFF_ZS);
    bf16* FTp  = (bf16*)(smem_c + OFF_FT);
    bf16* Wvp  = (bf16*)(smem_c + OFF_WVS);
    const u32 sbase = smem_u32(smem_c);

    const int tid  = threadIdx.x;
    const int lane = tid & 31;
    const int wid  = tid >> 5;
    const int g    = lane >> 2;
    const int li   = lane & 3;
    const int n    = blockIdx.x >> 8;
    const int ct   = blockIdx.x & 255;

    // ---- init: zero padded bf16 regions, load biases ----
    for (int i = tid; i < 5120; i += 256) ((u32*)ATp)[i] = 0;   // AT 20480 B
    for (int i = tid; i < 4352; i += 256) ((u32*)Vp)[i]  = 0;   // V  17408 B
    for (int i = tid; i < 3744; i += 256) ((u32*)Zp)[i]  = 0;   // Z  14976 B
    for (int i = tid; i < 3744; i += 256) ((u32*)FTp)[i] = 0;   // FT 14976 B
    if (tid < 64) bv_s[tid] = bv[tid];
    bo_s[tid] = bo[tid];
    __syncthreads();

    // AT fill: AT[h][v][u] = attn[h][u][v]
    for (int idx = tid; idx < Hh * Vv * Vv; idx += 256) {
        int h = idx / 625, rem = idx - h * 625;
        int u = rem / 25, v = rem - u * 25;
        ATp[h * 1280 + v * 40 + u] = __float2bfloat16(g_attn[idx]);
    }

    // ================= Stage V: V[64c][100col] = Wv @ F + bv =================
    const int v_mt  = wid & 3;
    const int v_nt0 = (wid >> 2) * 6;   // nt 0..6 / 6..12 (nt=6 duplicated, benign)
    float vacc[7][4];
#pragma unroll
    for (int i = 0; i < 7; i++)
#pragma unroll
        for (int j = 0; j < 4; j++) vacc[i][j] = 0.f;

    const float4* f4base = (const float4*)(f + (size_t)n * 6553600 + (size_t)ct * 100);

    for (int kc = 0; kc < 4; kc++) {
        // stage F^T: FT[col][k] bf16 (stride 72)
        for (int idx4 = tid; idx4 < 1600; idx4 += 256) {
            int r = idx4 / 25, q = idx4 - r * 25;
            float4 v4 = f4base[(size_t)(kc * 64 + r) * 6400 + q];
            bf16* p = FTp + (q * 4) * 72 + r;
            p[0]   = __float2bfloat16(v4.x);
            p[72]  = __float2bfloat16(v4.y);
            p[144] = __float2bfloat16(v4.z);
            p[216] = __float2bfloat16(v4.w);
        }
        // stage Wv chunk: Wv_s[c][k] bf16 (stride 72)
        for (int idx4 = tid; idx4 < 1024; idx4 += 256) {
            int row = idx4 >> 4, j = idx4 & 15;
            float4 v4 = *(const float4*)(Wv + row * 256 + kc * 64 + j * 4);
            __nv_bfloat162* p = (__nv_bfloat162*)(Wvp + row * 72 + j * 4);
            p[0] = __nv_bfloat162(__float2bfloat16(v4.x), __float2bfloat16(v4.y));
            p[1] = __nv_bfloat162(__float2bfloat16(v4.z), __float2bfloat16(v4.w));
        }
        __syncthreads();
#pragma unroll
        for (int ks = 0; ks < 4; ks++) {
            int k = ks * 16;
            const bf16* wb = Wvp + (v_mt * 16 + g) * 72 + k + 2 * li;
            u32 a0 = ld32(wb), a1 = ld32(wb + 8 * 72);
            u32 a2 = ld32(wb + 8), a3 = ld32(wb + 8 * 72 + 8);
#pragma unroll
            for (int i = 0; i < 7; i++) {
                int nt = v_nt0 + i;
                const bf16* fb = FTp + (nt * 8 + g) * 72 + k + 2 * li;
                mma16(vacc[i], a0, a1, a2, a3, ld32(fb), ld32(fb + 8));
            }
        }
        __syncthreads();
    }
    // V epilogue -> V_s bf16 [c][tl*32+u] (stride 136)
    {
        int r0 = v_mt * 16 + g;
        float bv0 = bv_s[r0], bv1 = bv_s[r0 + 8];
#pragma unroll
        for (int i = 0; i < 7; i++) {
            int col0 = (v_nt0 + i) * 8 + li * 2;
            if (col0 < 100) {
                int tl = col0 / 25, u = col0 - tl * 25;
                Vp[r0 * 136 + tl * 32 + u]       = __float2bfloat16(vacc[i][0] + bv0);
                Vp[(r0 + 8) * 136 + tl * 32 + u] = __float2bfloat16(vacc[i][2] + bv1);
                int c1 = col0 + 1;
                int tl1 = c1 / 25, u1 = c1 - tl1 * 25;
                Vp[r0 * 136 + tl1 * 32 + u1]       = __float2bfloat16(vacc[i][1] + bv0);
                Vp[(r0 + 8) * 136 + tl1 * 32 + u1] = __float2bfloat16(vacc[i][3] + bv1);
            }
        }
    }
    __syncthreads();   // V_s ready; FT/Wv region now free for Wo buffers

    // ================= Head loop: Z-gen + main mma, Wo double-buffered ========
    const int z_tl = wid & 3;
    const int z_mh = wid >> 2;
    float macc[2][13][4];
#pragma unroll
    for (int mi = 0; mi < 2; mi++)
#pragma unroll
        for (int nt = 0; nt < 13; nt++)
#pragma unroll
            for (int j = 0; j < 4; j++) macc[mi][nt][j] = 0.f;

    // prefetch Wo chunk 0 into buffer 0
    {
        const bf16* src = g_Wo_b;
        u32 dstb = sbase + OFF_WO;
#pragma unroll
        for (int it = 0; it < 8; it++) {
            int idx = tid + it * 256;
            int o = idx >> 3, j = idx & 7;
            cpasync16(dstb + o * 144 + j * 16, src + (size_t)o * 512 + j * 8);
        }
        asm volatile("cp.async.commit_group;");
    }

    for (int h = 0; h < 8; h++) {
        if (h) __syncthreads();   // mma(h-1) done reading Z_s

        // ---- Z-gen: Z[c][v] = V[c][u] @ attn_h[u][v], per t-slice z_tl ----
        float zacc[2][4][4];
#pragma unroll
        for (int mi = 0; mi < 2; mi++)
#pragma unroll
            for (int nt = 0; nt < 4; nt++)
#pragma unroll
                for (int j = 0; j < 4; j++) zacc[mi][nt][j] = 0.f;
#pragma unroll
        for (int ks = 0; ks < 2; ks++) {
            int k = ks * 16;
            u32 bb[4][2];
#pragma unroll
            for (int nt = 0; nt < 4; nt++) {
                const bf16* ab = ATp + h * 1280 + (nt * 8 + g) * 40 + k + 2 * li;
                bb[nt][0] = ld32(ab); bb[nt][1] = ld32(ab + 8);
            }
#pragma unroll
            for (int mi = 0; mi < 2; mi++) {
                const bf16* vb = Vp + (z_mh * 32 + mi * 16 + g) * 136
                                 + z_tl * 32 + k + 2 * li;
                u32 a0 = ld32(vb), a1 = ld32(vb + 8 * 136);
                u32 a2 = ld32(vb + 8), a3 = ld32(vb + 8 * 136 + 8);
#pragma unroll
                for (int nt = 0; nt < 4; nt++)
                    mma16(zacc[mi][nt], a0, a1, a2, a3, bb[nt][0], bb[nt][1]);
            }
        }
        // store Z^T: Zp[col][c] bf16 (stride 72)
#pragma unroll
        for (int mi = 0; mi < 2; mi++) {
            int c0 = z_mh * 32 + mi * 16 + g;
#pragma unroll
            for (int nt = 0; nt < 4; nt++) {
                int v0 = nt * 8 + 2 * li;
                if (v0 < 25) {
                    int col = z_tl * 25 + v0;
                    Zp[col * 72 + c0]     = __float2bfloat16(zacc[mi][nt][0]);
                    Zp[col * 72 + c0 + 8] = __float2bfloat16(zacc[mi][nt][2]);
                }
                if (v0 + 1 < 25) {
                    int col = z_tl * 25 + v0 + 1;
                    Zp[col * 72 + c0]     = __float2bfloat16(zacc[mi][nt][1]);
                    Zp[col * 72 + c0 + 8] = __float2bfloat16(zacc[mi][nt][3]);
                }
            }
        }
        asm volatile("cp.async.wait_group 0;" ::: "memory");
        __syncthreads();   // Wo buf (h&1) ready + Z_s visible

        // prefetch next Wo chunk into other buffer (overlaps mma below)
        if (h < 7) {
            const bf16* src = g_Wo_b + (h + 1) * 64;
            u32 dstb = sbase + OFF_WO + ((h + 1) & 1) * WO_BUF;
#pragma unroll
            for (int it = 0; it < 8; it++) {
                int idx = tid + it * 256;
                int o = idx >> 3, j = idx & 7;
                cpasync16(dstb + o * 144 + j * 16, src + (size_t)o * 512 + j * 8);
            }
            asm volatile("cp.async.commit_group;");
        }

        // ---- main mma: out[256][104] += Wo_h[256][64] @ Z[64][104] ----
        const bf16* Wop = (bf16*)(smem_c + OFF_WO + (h & 1) * WO_BUF);
#pragma unroll
        for (int ks = 0; ks < 4; ks++) {
            int k = ks * 16;
            u32 bz[13][2];
#pragma unroll
            for (int nt = 0; nt < 13; nt++) {
                const bf16* zb = Zp + (nt * 8 + g) * 72 + k + 2 * li;
                bz[nt][0] = ld32(zb); bz[nt][1] = ld32(zb + 8);
            }
#pragma unroll
            for (int mi = 0; mi < 2; mi++) {
                const bf16* wb = Wop + (wid * 32 + mi * 16 + g) * 72 + k + 2 * li;
                u32 a0 = ld32(wb), a1 = ld32(wb + 8 * 72);
                u32 a2 = ld32(wb + 8), a3 = ld32(wb + 8 * 72 + 8);
#pragma unroll
                for (int nt = 0; nt < 13; nt++)
                    mma16(macc[mi][nt], a0, a1, a2, a3, bz[nt][0], bz[nt][1]);
            }
        }
    }

    // ================= Epilogue: + bo + residual f (float2 stores) ============
    {
        const size_t base = (size_t)n * 6553600 + (size_t)ct * 100;
#pragma unroll
        for (int mi = 0; mi < 2; mi++) {
            int r0 = wid * 32 + mi * 16 + g;
            float bo0 = bo_s[r0], bo1 = bo_s[r0 + 8];
#pragma unroll
            for (int nt = 0; nt < 13; nt++) {
                int col0 = nt * 8 + li * 2;
                if (col0 < 100) {
                    size_t a0 = base + (size_t)r0 * 25600 + col0;
                    float2 fv0 = *(const float2*)(f + a0);
                    float2 ov0;
                    ov0.x = macc[mi][nt][0] + bo0 + fv0.x;
                    ov0.y = macc[mi][nt][1] + bo0 + fv0.y;
                    *(float2*)(out + a0) = ov0;
                    size_t a2 = base + (size_t)(r0 + 8) * 25600 + col0;
                    float2 fv2 = *(const float2*)(f + a2);
                    float2 ov2;
                    ov2.x = macc[mi][nt][2] + bo1 + fv2.x;
                    ov2.y = macc[mi][nt][3] + bo1 + fv2.y;
                    *(float2*)(out + a2) = ov2;
                }
            }
        }
    }
}

// ---------------------------------------------------------------------------
extern "C" void kernel_launch(void* const* d_in, const int* in_sizes, int n_in,
                              void* d_out, int out_size) {
    const float* feature = (const float*)d_in[0];
    const float* tf      = (const float*)d_in[1];
    const float* Wq      = (const float*)d_in[2];
    const float* bq      = (const float*)d_in[3];
    const float* Wk      = (const float*)d_in[4];
    const float* bk      = (const float*)d_in[5];
    const float* Wv      = (const float*)d_in[6];
    const float* bv      = (const float*)d_in[7];
    const float* Wo      = (const float*)d_in[8];
    const float* bo      = (const float*)d_in[9];
    float* out = (float*)d_out;

    const size_t qk_smem   = (size_t)HC * Vv * sizeof(float);
    const size_t attn_smem = (size_t)2 * HC * Vv * sizeof(float);

    cudaFuncSetAttribute((const void*)qk_kernel,
                         cudaFuncAttributeMaxDynamicSharedMemorySize, (int)qk_smem);
    cudaFuncSetAttribute((const void*)attn_kernel,
                         cudaFuncAttributeMaxDynamicSharedMemorySize, (int)attn_smem);
    cudaFuncSetAttribute((const void*)main_kernel,
                         cudaFuncAttributeMaxDynamicSharedMemorySize, SMEM_MAIN);

    qk_kernel<<<640, 256, qk_smem>>>(tf, Wq, bq, Wk, bk);
    attn_kernel<<<1, 256, attn_smem>>>();
    wo_prep<<<512, 256>>>(Wo);
    main_kernel<<<Nn * 256, 256, SMEM_MAIN>>>(feature, Wv, bv, bo, out);
}

// round 9
// speedup vs baseline: 1.6605x; 1.1633x over previous
#include <cuda_runtime.h>
#include <cuda_bf16.h>

// Problem constants
#define Nn 8
#define Cc 256
#define Tt 1024
#define Vv 25
#define Hh 8
#define Dd 64
#define HC 512

typedef unsigned int u32;
typedef unsigned long long u64;
typedef __nv_bfloat16 bf16;

// Precomputed globals
__device__ float g_q[HC * Vv];
__device__ float g_k[HC * Vv];
__device__ float g_attn[Hh * Vv * Vv];
__device__ bf16 g_Wo_b[256 * 512];

// ---------------- helpers ----------------
__device__ __forceinline__ void mma16(float* c, u32 a0, u32 a1, u32 a2, u32 a3,
                                      u32 b0, u32 b1) {
    asm("mma.sync.aligned.m16n8k16.row.col.f32.bf16.bf16.f32 "
        "{%0,%1,%2,%3}, {%4,%5,%6,%7}, {%8,%9}, {%0,%1,%2,%3};"
        : "+f"(c[0]), "+f"(c[1]), "+f"(c[2]), "+f"(c[3])
        : "r"(a0), "r"(a1), "r"(a2), "r"(a3), "r"(b0), "r"(b1));
}
__device__ __forceinline__ void cpasync16(u32 dst_smem, const void* src) {
    asm volatile("cp.async.cg.shared.global [%0], [%1], 16;" :: "r"(dst_smem), "l"(src));
}
__device__ __forceinline__ u32 smem_u32(const void* p) {
    return (u32)__cvta_generic_to_shared(p);
}
__device__ __forceinline__ u32 ld32(const bf16* p) { return *(const u32*)p; }

// SMEM byte offsets (main kernel)
#define OFF_BV   0        // 64 fp32
#define OFF_BO   256      // 256 fp32
#define OFF_AT   1280     // bf16 [8][32][40]      = 20480 B
#define OFF_VS   21760    // bf16 [64][136]        = 17408 B
#define OFF_ZS   39168    // bf16 [104][72]        = 14976 B
#define OFF_WO   54144    // bf16 2 x [256][72]    = 73728 B (union w/ FT+Wv below)
#define OFF_FT   54144    // bf16 [104][72]        = 14976 B (V-stage only)
#define OFF_WVS  69120    // bf16 [64][72]         =  9216 B (V-stage only)
#define WO_BUF   36864
#define SMEM_MAIN 127872

#define NTHREADS 512

// ---------------------------------------------------------------------------
// Kernel 1: q/k GEMV, warp-per-5-outputs. 640 blocks x 8 warps.
// ---------------------------------------------------------------------------
__global__ void qk_kernel(const float* __restrict__ tf,
                          const float* __restrict__ Wq, const float* __restrict__ bq,
                          const float* __restrict__ Wk, const float* __restrict__ bk) {
    extern __shared__ float tf_s[];
    for (int idx = threadIdx.x; idx < HC * Vv; idx += blockDim.x) tf_s[idx] = tf[idx];
    __syncthreads();

    int wid = threadIdx.x >> 5, lane = threadIdx.x & 31;
    int gw = blockIdx.x * 8 + wid;
    int which = gw >= 2560;
    int rowid = gw - which * 2560;
    int hc = rowid / 5;
    int u0 = (rowid - hc * 5) * 5;
    const float* wrow = (which ? Wk : Wq) + hc * 512;

    float acc[5] = {0, 0, 0, 0, 0};
#pragma unroll
    for (int i = 0; i < 16; i++) {
        int k = i * 32 + lane;
        float w = wrow[k];
        const float* tb = tf_s + k * Vv + u0;
#pragma unroll
        for (int j = 0; j < 5; j++) acc[j] += w * tb[j];
    }
#pragma unroll
    for (int j = 0; j < 5; j++)
#pragma unroll
        for (int off = 16; off; off >>= 1)
            acc[j] += __shfl_xor_sync(0xFFFFFFFF, acc[j], off);

    if (lane == 0) {
        float b = (which ? bk : bq)[hc];
        float* dst = (which ? g_k : g_q) + hc * Vv + u0;
#pragma unroll
        for (int j = 0; j < 5; j++) dst[j] = acc[j] + b;
    }
}

// ---------------------------------------------------------------------------
// Kernel 2: energy + softmax -> g_attn
// ---------------------------------------------------------------------------
__global__ void attn_kernel() {
    extern __shared__ float s[];
    float* q_s = s;
    float* k_s = s + HC * Vv;
    for (int idx = threadIdx.x; idx < HC * Vv; idx += blockDim.x) {
        q_s[idx] = g_q[idx];
        k_s[idx] = g_k[idx];
    }
    __syncthreads();

    int r = threadIdx.x;
    if (r < Hh * Vv) {
        int h = r / Vv;
        int u = r - h * Vv;
        float e[Vv];
#pragma unroll
        for (int j = 0; j < Vv; j++) e[j] = 0.f;
        const float* qb = q_s + h * Dd * Vv;
        const float* kb = k_s + h * Dd * Vv;
        for (int c = 0; c < Dd; c++) {
            float qv = qb[c * Vv + u];
#pragma unroll
            for (int j = 0; j < Vv; j++) e[j] += qv * kb[c * Vv + j];
        }
        float m = -1e30f;
#pragma unroll
        for (int j = 0; j < Vv; j++) { e[j] *= 0.125f; m = fmaxf(m, e[j]); }
        float ssum = 0.f;
#pragma unroll
        for (int j = 0; j < Vv; j++) { e[j] = expf(e[j] - m); ssum += e[j]; }
        float inv = 1.f / ssum;
        float* arow = g_attn + (h * Vv + u) * Vv;
#pragma unroll
        for (int j = 0; j < Vv; j++) arow[j] = e[j] * inv;
    }
}

// ---------------------------------------------------------------------------
// Kernel 2b: Wo -> bf16 prep
// ---------------------------------------------------------------------------
__global__ void wo_prep(const float* __restrict__ Wo) {
    int i = blockIdx.x * 256 + threadIdx.x;
    g_Wo_b[i] = __float2bfloat16(Wo[i]);
}

// ---------------------------------------------------------------------------
// Kernel 3 (main): one block per (n, 100 cols). 512 threads / 16 warps.
// ---------------------------------------------------------------------------
__global__ void __launch_bounds__(NTHREADS, 1)
main_kernel(const float* __restrict__ f, const float* __restrict__ Wv,
            const float* __restrict__ bv, const float* __restrict__ bo,
            float* __restrict__ out) {
    extern __shared__ char smem_c[];
    float* bv_s = (float*)(smem_c + OFF_BV);
    float* bo_s = (float*)(smem_c + OFF_BO);
    bf16* ATp  = (bf16*)(smem_c + OFF_AT);
    bf16* Vp   = (bf16*)(smem_c + OFF_VS);
    bf16* Zp   = (bf16*)(smem_c + OFF_ZS);
    bf16* FTp  = (bf16*)(smem_c + OFF_FT);
    bf16* Wvp  = (bf16*)(smem_c + OFF_WVS);
    const u32 sbase = smem_u32(smem_c);

    const int tid  = threadIdx.x;
    const int lane = tid & 31;
    const int wid  = tid >> 5;          // 0..15
    const int g    = lane >> 2;
    const int li   = lane & 3;
    const int n    = blockIdx.x >> 8;
    const int ct   = blockIdx.x & 255;

    // ---- init: zero padded bf16 regions, load biases ----
    for (int i = tid; i < 5120; i += NTHREADS) ((u32*)ATp)[i] = 0;
    for (int i = tid; i < 4352; i += NTHREADS) ((u32*)Vp)[i]  = 0;
    for (int i = tid; i < 3744; i += NTHREADS) ((u32*)Zp)[i]  = 0;
    for (int i = tid; i < 3744; i += NTHREADS) ((u32*)FTp)[i] = 0;
    if (tid < 64) bv_s[tid] = bv[tid];
    if (tid < 256) bo_s[tid] = bo[tid];
    __syncthreads();

    // AT fill: AT[h][v][u] = attn[h][u][v]
    for (int idx = tid; idx < Hh * Vv * Vv; idx += NTHREADS) {
        int h = idx / 625, rem = idx - h * 625;
        int u = rem / 25, v = rem - u * 25;
        ATp[h * 1280 + v * 40 + u] = __float2bfloat16(g_attn[idx]);
    }

    // ================= Stage V: V[64c][100col] = Wv @ F + bv =================
    const int v_mt  = wid & 3;           // m-tile (16 rows)
    const int v_nt0 = (wid >> 2) * 4;    // nt group: {0,4,8,12}, 4 each, guard <13
    float vacc[4][4];
#pragma unroll
    for (int i = 0; i < 4; i++)
#pragma unroll
        for (int j = 0; j < 4; j++) vacc[i][j] = 0.f;

    const float4* f4base = (const float4*)(f + (size_t)n * 6553600 + (size_t)ct * 100);

    for (int kc = 0; kc < 4; kc++) {
        // stage F^T: FT[col][k] bf16 (stride 72)
        for (int idx4 = tid; idx4 < 1600; idx4 += NTHREADS) {
            int r = idx4 / 25, q = idx4 - r * 25;
            float4 v4 = f4base[(size_t)(kc * 64 + r) * 6400 + q];
            bf16* p = FTp + (q * 4) * 72 + r;
            p[0]   = __float2bfloat16(v4.x);
            p[72]  = __float2bfloat16(v4.y);
            p[144] = __float2bfloat16(v4.z);
            p[216] = __float2bfloat16(v4.w);
        }
        // stage Wv chunk: Wv_s[c][k] bf16 (stride 72)
        for (int idx4 = tid; idx4 < 1024; idx4 += NTHREADS) {
            int row = idx4 >> 4, j = idx4 & 15;
            float4 v4 = *(const float4*)(Wv + row * 256 + kc * 64 + j * 4);
            __nv_bfloat162* p = (__nv_bfloat162*)(Wvp + row * 72 + j * 4);
            p[0] = __nv_bfloat162(__float2bfloat16(v4.x), __float2bfloat16(v4.y));
            p[1] = __nv_bfloat162(__float2bfloat16(v4.z), __float2bfloat16(v4.w));
        }
        __syncthreads();
#pragma unroll
        for (int ks = 0; ks < 4; ks++) {
            int k = ks * 16;
            const bf16* wb = Wvp + (v_mt * 16 + g) * 72 + k + 2 * li;
            u32 a0 = ld32(wb), a1 = ld32(wb + 8 * 72);
            u32 a2 = ld32(wb + 8), a3 = ld32(wb + 8 * 72 + 8);
#pragma unroll
            for (int i = 0; i < 4; i++) {
                int nt = v_nt0 + i;
                if (nt < 13) {
                    const bf16* fb = FTp + (nt * 8 + g) * 72 + k + 2 * li;
                    mma16(vacc[i], a0, a1, a2, a3, ld32(fb), ld32(fb + 8));
                }
            }
        }
        __syncthreads();
    }
    // V epilogue -> V_s bf16 [c][tl*32+u] (stride 136)
    {
        int r0 = v_mt * 16 + g;
        float bv0 = bv_s[r0], bv1 = bv_s[r0 + 8];
#pragma unroll
        for (int i = 0; i < 4; i++) {
            int nt = v_nt0 + i;
            int col0 = nt * 8 + li * 2;
            if (nt < 13 && col0 < 100) {
                int tl = col0 / 25, u = col0 - tl * 25;
                Vp[r0 * 136 + tl * 32 + u]       = __float2bfloat16(vacc[i][0] + bv0);
                Vp[(r0 + 8) * 136 + tl * 32 + u] = __float2bfloat16(vacc[i][2] + bv1);
                int c1 = col0 + 1;
                int tl1 = c1 / 25, u1 = c1 - tl1 * 25;
                Vp[r0 * 136 + tl1 * 32 + u1]       = __float2bfloat16(vacc[i][1] + bv0);
                Vp[(r0 + 8) * 136 + tl1 * 32 + u1] = __float2bfloat16(vacc[i][3] + bv1);
            }
        }
    }
    __syncthreads();   // V_s ready; FT/Wv region now free for Wo buffers

    // ================= Head loop: Z-gen + main mma, Wo double-buffered ========
    const int z_tl = wid & 3;        // t-slice
    const int z_c  = wid >> 2;       // c-quarter (16 rows)
    float macc[13][4];
#pragma unroll
    for (int nt = 0; nt < 13; nt++)
#pragma unroll
        for (int j = 0; j < 4; j++) macc[nt][j] = 0.f;

    // prefetch Wo chunk 0 into buffer 0
    {
        const bf16* src = g_Wo_b;
        u32 dstb = sbase + OFF_WO;
#pragma unroll
        for (int it = 0; it < 4; it++) {
            int idx = tid + it * NTHREADS;
            int o = idx >> 3, j = idx & 7;
            cpasync16(dstb + o * 144 + j * 16, src + (size_t)o * 512 + j * 8);
        }
        asm volatile("cp.async.commit_group;");
    }

    for (int h = 0; h < 8; h++) {
        if (h) __syncthreads();   // mma(h-1) done reading Z_s

        // ---- Z-gen: Z[c][v] = V[c][u] @ attn_h[u][v] ----
        float zacc[4][4];
#pragma unroll
        for (int nt = 0; nt < 4; nt++)
#pragma unroll
            for (int j = 0; j < 4; j++) zacc[nt][j] = 0.f;
#pragma unroll
        for (int ks = 0; ks < 2; ks++) {
            int k = ks * 16;
            const bf16* vb = Vp + (z_c * 16 + g) * 136 + z_tl * 32 + k + 2 * li;
            u32 a0 = ld32(vb), a1 = ld32(vb + 8 * 136);
            u32 a2 = ld32(vb + 8), a3 = ld32(vb + 8 * 136 + 8);
#pragma unroll
            for (int nt = 0; nt < 4; nt++) {
                const bf16* ab = ATp + h * 1280 + (nt * 8 + g) * 40 + k + 2 * li;
                mma16(zacc[nt], a0, a1, a2, a3, ld32(ab), ld32(ab + 8));
            }
        }
        // store Z^T: Zp[col][c] bf16 (stride 72)
        {
            int c0 = z_c * 16 + g;
#pragma unroll
            for (int nt = 0; nt < 4; nt++) {
                int v0 = nt * 8 + 2 * li;
                if (v0 < 25) {
                    int col = z_tl * 25 + v0;
                    Zp[col * 72 + c0]     = __float2bfloat16(zacc[nt][0]);
                    Zp[col * 72 + c0 + 8] = __float2bfloat16(zacc[nt][2]);
                }
                if (v0 + 1 < 25) {
                    int col = z_tl * 25 + v0 + 1;
                    Zp[col * 72 + c0]     = __float2bfloat16(zacc[nt][1]);
                    Zp[col * 72 + c0 + 8] = __float2bfloat16(zacc[nt][3]);
                }
            }
        }
        asm volatile("cp.async.wait_group 0;" ::: "memory");
        __syncthreads();   // Wo buf (h&1) ready + Z_s visible

        // prefetch next Wo chunk into other buffer (overlaps mma below)
        if (h < 7) {
            const bf16* src = g_Wo_b + (h + 1) * 64;
            u32 dstb = sbase + OFF_WO + ((h + 1) & 1) * WO_BUF;
#pragma unroll
            for (int it = 0; it < 4; it++) {
                int idx = tid + it * NTHREADS;
                int o = idx >> 3, j = idx & 7;
                cpasync16(dstb + o * 144 + j * 16, src + (size_t)o * 512 + j * 8);
            }
            asm volatile("cp.async.commit_group;");
        }

        // ---- main mma: out[256][104] += Wo_h[256][64] @ Z[64][104] ----
        // each warp: one 16-row m-tile (wid*16)
        const bf16* Wop = (bf16*)(smem_c + OFF_WO + (h & 1) * WO_BUF);
#pragma unroll
        for (int ks = 0; ks < 4; ks++) {
            int k = ks * 16;
            const bf16* wb = Wop + (wid * 16 + g) * 72 + k + 2 * li;
            u32 a0 = ld32(wb), a1 = ld32(wb + 8 * 72);
            u32 a2 = ld32(wb + 8), a3 = ld32(wb + 8 * 72 + 8);
#pragma unroll
            for (int nt = 0; nt < 13; nt++) {
                const bf16* zb = Zp + (nt * 8 + g) * 72 + k + 2 * li;
                mma16(macc[nt], a0, a1, a2, a3, ld32(zb), ld32(zb + 8));
            }
        }
    }

    // ================= Epilogue: + bo + residual f (float2 stores) ============
    {
        const size_t base = (size_t)n * 6553600 + (size_t)ct * 100;
        int r0 = wid * 16 + g;
        float bo0 = bo_s[r0], bo1 = bo_s[r0 + 8];
#pragma unroll
        for (int nt = 0; nt < 13; nt++) {
            int col0 = nt * 8 + li * 2;
            if (col0 < 100) {
                size_t a0 = base + (size_t)r0 * 25600 + col0;
                float2 fv0 = *(const float2*)(f + a0);
                float2 ov0;
                ov0.x = macc[nt][0] + bo0 + fv0.x;
                ov0.y = macc[nt][1] + bo0 + fv0.y;
                *(float2*)(out + a0) = ov0;
                size_t a2 = base + (size_t)(r0 + 8) * 25600 + col0;
                float2 fv2 = *(const float2*)(f + a2);
                float2 ov2;
                ov2.x = macc[nt][2] + bo1 + fv2.x;
                ov2.y = macc[nt][3] + bo1 + fv2.y;
                *(float2*)(out + a2) = ov2;
            }
        }
    }
}

// ---------------------------------------------------------------------------
extern "C" void kernel_launch(void* const* d_in, const int* in_sizes, int n_in,
                              void* d_out, int out_size) {
    const float* feature = (const float*)d_in[0];
    const float* tf      = (const float*)d_in[1];
    const float* Wq      = (const float*)d_in[2];
    const float* bq      = (const float*)d_in[3];
    const float* Wk      = (const float*)d_in[4];
    const float* bk      = (const float*)d_in[5];
    const float* Wv      = (const float*)d_in[6];
    const float* bv      = (const float*)d_in[7];
    const float* Wo      = (const float*)d_in[8];
    const float* bo      = (const float*)d_in[9];
    float* out = (float*)d_out;

    const size_t qk_smem   = (size_t)HC * Vv * sizeof(float);
    const size_t attn_smem = (size_t)2 * HC * Vv * sizeof(float);

    cudaFuncSetAttribute((const void*)qk_kernel,
                         cudaFuncAttributeMaxDynamicSharedMemorySize, (int)qk_smem);
    cudaFuncSetAttribute((const void*)attn_kernel,
                         cudaFuncAttributeMaxDynamicSharedMemorySize, (int)attn_smem);
    cudaFuncSetAttribute((const void*)main_kernel,
                         cudaFuncAttributeMaxDynamicSharedMemorySize, SMEM_MAIN);

    qk_kernel<<<640, 256, qk_smem>>>(tf, Wq, bq, Wk, bk);
    attn_kernel<<<1, 256, attn_smem>>>();
    wo_prep<<<512, 256>>>(Wo);
    main_kernel<<<Nn * 256, NTHREADS, SMEM_MAIN>>>(feature, Wv, bv, bo, out);
}

// round 10
// speedup vs baseline: 1.7210x; 1.0364x over previous
#include <cuda_runtime.h>
#include <cuda_bf16.h>

// Problem constants
#define Nn 8
#define Cc 256
#define Tt 1024
#define Vv 25
#define Hh 8
#define Dd 64
#define HC 512

typedef unsigned int u32;
typedef unsigned long long u64;
typedef __nv_bfloat16 bf16;

// Precomputed globals
__device__ float g_q[HC * Vv];
__device__ float g_k[HC * Vv];
__device__ float g_attn[Hh * Vv * Vv];
__device__ bf16 g_Wo_b[256 * 512];

// ---------------- helpers ----------------
__device__ __forceinline__ void mma16(float* c, u32 a0, u32 a1, u32 a2, u32 a3,
                                      u32 b0, u32 b1) {
    asm("mma.sync.aligned.m16n8k16.row.col.f32.bf16.bf16.f32 "
        "{%0,%1,%2,%3}, {%4,%5,%6,%7}, {%8,%9}, {%0,%1,%2,%3};"
        : "+f"(c[0]), "+f"(c[1]), "+f"(c[2]), "+f"(c[3])
        : "r"(a0), "r"(a1), "r"(a2), "r"(a3), "r"(b0), "r"(b1));
}
__device__ __forceinline__ void ldsm4(u32& r0, u32& r1, u32& r2, u32& r3, u32 a) {
    asm volatile("ldmatrix.sync.aligned.m8n8.x4.shared.b16 {%0,%1,%2,%3}, [%4];"
                 : "=r"(r0), "=r"(r1), "=r"(r2), "=r"(r3) : "r"(a));
}
__device__ __forceinline__ void ldsm2(u32& r0, u32& r1, u32 a) {
    asm volatile("ldmatrix.sync.aligned.m8n8.x2.shared.b16 {%0,%1}, [%2];"
                 : "=r"(r0), "=r"(r1) : "r"(a));
}
__device__ __forceinline__ void cpasync16(u32 dst_smem, const void* src) {
    asm volatile("cp.async.cg.shared.global [%0], [%1], 16;" :: "r"(dst_smem), "l"(src));
}
__device__ __forceinline__ u32 smem_u32(const void* p) {
    return (u32)__cvta_generic_to_shared(p);
}

// SMEM byte offsets (main kernel)
#define OFF_BV   0        // 64 fp32
#define OFF_BO   256      // 256 fp32
#define OFF_AT   1280     // bf16 [8][32][40]      = 20480 B
#define OFF_VS   21760    // bf16 [64][136]        = 17408 B
#define OFF_ZS   39168    // bf16 [104][72]        = 14976 B
#define OFF_WO   54144    // bf16 2 x [256][72]    = 73728 B (union w/ FT+Wv below)
#define OFF_FT   54144    // bf16 [104][72]        = 14976 B (V-stage only)
#define OFF_WVS  69120    // bf16 [64][72]         =  9216 B (V-stage only)
#define WO_BUF   36864
#define SMEM_MAIN 127872

#define NTHREADS 512

// ---------------------------------------------------------------------------
// Kernel 1: q/k GEMV, warp-per-5-outputs. 640 blocks x 8 warps.
// ---------------------------------------------------------------------------
__global__ void qk_kernel(const float* __restrict__ tf,
                          const float* __restrict__ Wq, const float* __restrict__ bq,
                          const float* __restrict__ Wk, const float* __restrict__ bk) {
    extern __shared__ float tf_s[];
    for (int idx = threadIdx.x; idx < HC * Vv; idx += blockDim.x) tf_s[idx] = tf[idx];
    __syncthreads();

    int wid = threadIdx.x >> 5, lane = threadIdx.x & 31;
    int gw = blockIdx.x * 8 + wid;
    int which = gw >= 2560;
    int rowid = gw - which * 2560;
    int hc = rowid / 5;
    int u0 = (rowid - hc * 5) * 5;
    const float* wrow = (which ? Wk : Wq) + hc * 512;

    float acc[5] = {0, 0, 0, 0, 0};
#pragma unroll
    for (int i = 0; i < 16; i++) {
        int k = i * 32 + lane;
        float w = wrow[k];
        const float* tb = tf_s + k * Vv + u0;
#pragma unroll
        for (int j = 0; j < 5; j++) acc[j] += w * tb[j];
    }
#pragma unroll
    for (int j = 0; j < 5; j++)
#pragma unroll
        for (int off = 16; off; off >>= 1)
            acc[j] += __shfl_xor_sync(0xFFFFFFFF, acc[j], off);

    if (lane == 0) {
        float b = (which ? bk : bq)[hc];
        float* dst = (which ? g_k : g_q) + hc * Vv + u0;
#pragma unroll
        for (int j = 0; j < 5; j++) dst[j] = acc[j] + b;
    }
}

// ---------------------------------------------------------------------------
// Kernel 2: energy + softmax -> g_attn
// ---------------------------------------------------------------------------
__global__ void attn_kernel() {
    extern __shared__ float s[];
    float* q_s = s;
    float* k_s = s + HC * Vv;
    for (int idx = threadIdx.x; idx < HC * Vv; idx += blockDim.x) {
        q_s[idx] = g_q[idx];
        k_s[idx] = g_k[idx];
    }
    __syncthreads();

    int r = threadIdx.x;
    if (r < Hh * Vv) {
        int h = r / Vv;
        int u = r - h * Vv;
        float e[Vv];
#pragma unroll
        for (int j = 0; j < Vv; j++) e[j] = 0.f;
        const float* qb = q_s + h * Dd * Vv;
        const float* kb = k_s + h * Dd * Vv;
        for (int c = 0; c < Dd; c++) {
            float qv = qb[c * Vv + u];
#pragma unroll
            for (int j = 0; j < Vv; j++) e[j] += qv * kb[c * Vv + j];
        }
        float m = -1e30f;
#pragma unroll
        for (int j = 0; j < Vv; j++) { e[j] *= 0.125f; m = fmaxf(m, e[j]); }
        float ssum = 0.f;
#pragma unroll
        for (int j = 0; j < Vv; j++) { e[j] = expf(e[j] - m); ssum += e[j]; }
        float inv = 1.f / ssum;
        float* arow = g_attn + (h * Vv + u) * Vv;
#pragma unroll
        for (int j = 0; j < Vv; j++) arow[j] = e[j] * inv;
    }
}

// ---------------------------------------------------------------------------
// Kernel 2b: Wo -> bf16 prep
// ---------------------------------------------------------------------------
__global__ void wo_prep(const float* __restrict__ Wo) {
    int i = blockIdx.x * 256 + threadIdx.x;
    g_Wo_b[i] = __float2bfloat16(Wo[i]);
}

// ---------------------------------------------------------------------------
// Kernel 3 (main): one block per (n, 100 cols). 512 threads / 16 warps.
// Fragment loads via ldmatrix (LDSM).
// ---------------------------------------------------------------------------
__global__ void __launch_bounds__(NTHREADS, 1)
main_kernel(const float* __restrict__ f, const float* __restrict__ Wv,
            const float* __restrict__ bv, const float* __restrict__ bo,
            float* __restrict__ out) {
    extern __shared__ char smem_c[];
    float* bv_s = (float*)(smem_c + OFF_BV);
    float* bo_s = (float*)(smem_c + OFF_BO);
    bf16* ATp  = (bf16*)(smem_c + OFF_AT);
    bf16* Vp   = (bf16*)(smem_c + OFF_VS);
    bf16* Zp   = (bf16*)(smem_c + OFF_ZS);
    bf16* FTp  = (bf16*)(smem_c + OFF_FT);
    bf16* Wvp  = (bf16*)(smem_c + OFF_WVS);
    const u32 sbase = smem_u32(smem_c);

    const int tid  = threadIdx.x;
    const int lane = tid & 31;
    const int wid  = tid >> 5;          // 0..15
    const int g    = lane >> 2;
    const int li   = lane & 3;
    const int n    = blockIdx.x >> 8;
    const int ct   = blockIdx.x & 255;

    // ldmatrix per-lane address patterns
    const int lq = lane >> 3, lr = lane & 7;
    const int arow = ((lq & 1) << 3) + lr;   // A: tiles (m, m+8) x (k, k+8)
    const int acol = (lq >> 1) << 4;         // bytes
    const int brow = ((lq >> 1) << 3) + lr;  // B: tiles (n)x(k,k+8),(n+8)x(k,k+8)
    const int bcol = (lq & 1) << 4;          // bytes

    // ---- init: zero padded bf16 regions, load biases ----
    for (int i = tid; i < 5120; i += NTHREADS) ((u32*)ATp)[i] = 0;
    for (int i = tid; i < 4352; i += NTHREADS) ((u32*)Vp)[i]  = 0;
    for (int i = tid; i < 3744; i += NTHREADS) ((u32*)Zp)[i]  = 0;
    for (int i = tid; i < 3744; i += NTHREADS) ((u32*)FTp)[i] = 0;
    if (tid < 64) bv_s[tid] = bv[tid];
    if (tid < 256) bo_s[tid] = bo[tid];
    __syncthreads();

    // AT fill: AT[h][v][u] = attn[h][u][v]
    for (int idx = tid; idx < Hh * Vv * Vv; idx += NTHREADS) {
        int h = idx / 625, rem = idx - h * 625;
        int u = rem / 25, v = rem - u * 25;
        ATp[h * 1280 + v * 40 + u] = __float2bfloat16(g_attn[idx]);
    }

    // ================= Stage V: V[64c][100col] = Wv @ F + bv =================
    const int v_mt  = wid & 3;           // m-tile (16 rows)
    const int v_nt0 = (wid >> 2) * 4;    // nt group {0,4,8,12}
    float vacc[4][4];
#pragma unroll
    for (int i = 0; i < 4; i++)
#pragma unroll
        for (int j = 0; j < 4; j++) vacc[i][j] = 0.f;

    const float4* f4base = (const float4*)(f + (size_t)n * 6553600 + (size_t)ct * 100);
    const u32 aW_base = sbase + OFF_WVS + (u32)(v_mt * 16 + arow) * 144 + acol;
    const u32 bF_base = sbase + OFF_FT + (u32)brow * 144 + bcol + (u32)v_nt0 * 1152;

    for (int kc = 0; kc < 4; kc++) {
        // stage F^T: FT[col][k] bf16 (stride 72)
        for (int idx4 = tid; idx4 < 1600; idx4 += NTHREADS) {
            int r = idx4 / 25, q = idx4 - r * 25;
            float4 v4 = f4base[(size_t)(kc * 64 + r) * 6400 + q];
            bf16* p = FTp + (q * 4) * 72 + r;
            p[0]   = __float2bfloat16(v4.x);
            p[72]  = __float2bfloat16(v4.y);
            p[144] = __float2bfloat16(v4.z);
            p[216] = __float2bfloat16(v4.w);
        }
        // stage Wv chunk: Wv_s[c][k] bf16 (stride 72)
        for (int idx4 = tid; idx4 < 1024; idx4 += NTHREADS) {
            int row = idx4 >> 4, j = idx4 & 15;
            float4 v4 = *(const float4*)(Wv + row * 256 + kc * 64 + j * 4);
            __nv_bfloat162* p = (__nv_bfloat162*)(Wvp + row * 72 + j * 4);
            p[0] = __nv_bfloat162(__float2bfloat16(v4.x), __float2bfloat16(v4.y));
            p[1] = __nv_bfloat162(__float2bfloat16(v4.z), __float2bfloat16(v4.w));
        }
        __syncthreads();
#pragma unroll
        for (int ks = 0; ks < 4; ks++) {
            u32 koff = ks * 32;
            u32 a0, a1, a2, a3;
            ldsm4(a0, a1, a2, a3, aW_base + koff);
#pragma unroll
            for (int p = 0; p < 2; p++) {
                int nt = v_nt0 + 2 * p;
                u32 b0, b1, b2, b3;
                ldsm4(b0, b1, b2, b3, bF_base + (u32)(2 * p) * 1152 + koff);
                if (nt < 13)     mma16(vacc[2 * p],     a0, a1, a2, a3, b0, b1);
                if (nt + 1 < 13) mma16(vacc[2 * p + 1], a0, a1, a2, a3, b2, b3);
            }
        }
        __syncthreads();
    }
    // V epilogue -> V_s bf16 [c][tl*32+u] (stride 136)
    {
        int r0 = v_mt * 16 + g;
        float bv0 = bv_s[r0], bv1 = bv_s[r0 + 8];
#pragma unroll
        for (int i = 0; i < 4; i++) {
            int nt = v_nt0 + i;
            int col0 = nt * 8 + li * 2;
            if (nt < 13 && col0 < 100) {
                int tl = col0 / 25, u = col0 - tl * 25;
                Vp[r0 * 136 + tl * 32 + u]       = __float2bfloat16(vacc[i][0] + bv0);
                Vp[(r0 + 8) * 136 + tl * 32 + u] = __float2bfloat16(vacc[i][2] + bv1);
                int c1 = col0 + 1;
                int tl1 = c1 / 25, u1 = c1 - tl1 * 25;
                Vp[r0 * 136 + tl1 * 32 + u1]       = __float2bfloat16(vacc[i][1] + bv0);
                Vp[(r0 + 8) * 136 + tl1 * 32 + u1] = __float2bfloat16(vacc[i][3] + bv1);
            }
        }
    }
    __syncthreads();   // V_s ready; FT/Wv region now free for Wo buffers

    // ================= Head loop: Z-gen + main mma, Wo double-buffered ========
    const int z_tl = wid & 3;        // t-slice
    const int z_c  = wid >> 2;       // c-quarter (16 rows)
    float macc[13][4];
#pragma unroll
    for (int nt = 0; nt < 13; nt++)
#pragma unroll
        for (int j = 0; j < 4; j++) macc[nt][j] = 0.f;

    const u32 aV_base = sbase + OFF_VS + (u32)(z_c * 16 + arow) * 272
                        + (u32)z_tl * 64 + acol;
    const u32 bA_base = sbase + OFF_AT + (u32)brow * 80 + bcol;
    const u32 bZ_base = sbase + OFF_ZS + (u32)brow * 144 + bcol;
    const u32 aO_base = sbase + OFF_WO + (u32)(wid * 16 + arow) * 144 + acol;

    // prefetch Wo chunk 0 into buffer 0
    {
        const bf16* src = g_Wo_b;
        u32 dstb = sbase + OFF_WO;
#pragma unroll
        for (int it = 0; it < 4; it++) {
            int idx = tid + it * NTHREADS;
            int o = idx >> 3, j = idx & 7;
            cpasync16(dstb + o * 144 + j * 16, src + (size_t)o * 512 + j * 8);
        }
        asm volatile("cp.async.commit_group;");
    }

    for (int h = 0; h < 8; h++) {
        if (h) __syncthreads();   // mma(h-1) done reading Z_s

        // ---- Z-gen: Z[c][v] = V[c][u] @ attn_h[u][v] ----
        float zacc[4][4];
#pragma unroll
        for (int nt = 0; nt < 4; nt++)
#pragma unroll
            for (int j = 0; j < 4; j++) zacc[nt][j] = 0.f;
#pragma unroll
        for (int ks = 0; ks < 2; ks++) {
            u32 koff = ks * 32;
            u32 a0, a1, a2, a3;
            ldsm4(a0, a1, a2, a3, aV_base + koff);
#pragma unroll
            for (int p = 0; p < 2; p++) {
                u32 b0, b1, b2, b3;
                ldsm4(b0, b1, b2, b3, bA_base + h * 2560 + (u32)p * 1280 + koff);
                mma16(zacc[2 * p],     a0, a1, a2, a3, b0, b1);
                mma16(zacc[2 * p + 1], a0, a1, a2, a3, b2, b3);
            }
        }
        // store Z^T: Zp[col][c] bf16 (stride 72)
        {
            int c0 = z_c * 16 + g;
#pragma unroll
            for (int nt = 0; nt < 4; nt++) {
                int v0 = nt * 8 + 2 * li;
                if (v0 < 25) {
                    int col = z_tl * 25 + v0;
                    Zp[col * 72 + c0]     = __float2bfloat16(zacc[nt][0]);
                    Zp[col * 72 + c0 + 8] = __float2bfloat16(zacc[nt][2]);
                }
                if (v0 + 1 < 25) {
                    int col = z_tl * 25 + v0 + 1;
                    Zp[col * 72 + c0]     = __float2bfloat16(zacc[nt][1]);
                    Zp[col * 72 + c0 + 8] = __float2bfloat16(zacc[nt][3]);
                }
            }
        }
        asm volatile("cp.async.wait_group 0;" ::: "memory");
        __syncthreads();   // Wo buf (h&1) ready + Z_s visible

        // prefetch next Wo chunk into other buffer (overlaps mma below)
        if (h < 7) {
            const bf16* src = g_Wo_b + (h + 1) * 64;
            u32 dstb = sbase + OFF_WO + ((h + 1) & 1) * WO_BUF;
#pragma unroll
            for (int it = 0; it < 4; it++) {
                int idx = tid + it * NTHREADS;
                int o = idx >> 3, j = idx & 7;
                cpasync16(dstb + o * 144 + j * 16, src + (size_t)o * 512 + j * 8);
            }
            asm volatile("cp.async.commit_group;");
        }

        // ---- main mma: out[256][104] += Wo_h[256][64] @ Z[64][104] ----
        const u32 aO = aO_base + (h & 1) * WO_BUF;
#pragma unroll
        for (int ks = 0; ks < 4; ks++) {
            u32 koff = ks * 32;
            u32 a0, a1, a2, a3;
            ldsm4(a0, a1, a2, a3, aO + koff);
#pragma unroll
            for (int p = 0; p < 6; p++) {
                u32 b0, b1, b2, b3;
                ldsm4(b0, b1, b2, b3, bZ_base + (u32)(2 * p) * 1152 + koff);
                mma16(macc[2 * p],     a0, a1, a2, a3, b0, b1);
                mma16(macc[2 * p + 1], a0, a1, a2, a3, b2, b3);
            }
            u32 b0, b1;
            ldsm2(b0, b1, bZ_base + 12u * 1152 + koff);
            mma16(macc[12], a0, a1, a2, a3, b0, b1);
        }
    }

    // ================= Epilogue: + bo + residual f (float2 stores) ============
    {
        const size_t base = (size_t)n * 6553600 + (size_t)ct * 100;
        int r0 = wid * 16 + g;
        float bo0 = bo_s[r0], bo1 = bo_s[r0 + 8];
#pragma unroll
        for (int nt = 0; nt < 13; nt++) {
            int col0 = nt * 8 + li * 2;
            if (col0 < 100) {
                size_t a0 = base + (size_t)r0 * 25600 + col0;
                float2 fv0 = *(const float2*)(f + a0);
                float2 ov0;
                ov0.x = macc[nt][0] + bo0 + fv0.x;
                ov0.y = macc[nt][1] + bo0 + fv0.y;
                *(float2*)(out + a0) = ov0;
                size_t a2 = base + (size_t)(r0 + 8) * 25600 + col0;
                float2 fv2 = *(const float2*)(f + a2);
                float2 ov2;
                ov2.x = macc[nt][2] + bo1 + fv2.x;
                ov2.y = macc[nt][3] + bo1 + fv2.y;
                *(float2*)(out + a2) = ov2;
            }
        }
    }
}

// ---------------------------------------------------------------------------
extern "C" void kernel_launch(void* const* d_in, const int* in_sizes, int n_in,
                              void* d_out, int out_size) {
    const float* feature = (const float*)d_in[0];
    const float* tf      = (const float*)d_in[1];
    const float* Wq      = (const float*)d_in[2];
    const float* bq      = (const float*)d_in[3];
    const float* Wk      = (const float*)d_in[4];
    const float* bk      = (const float*)d_in[5];
    const float* Wv      = (const float*)d_in[6];
    const float* bv      = (const float*)d_in[7];
    const float* Wo      = (const float*)d_in[8];
    const float* bo      = (const float*)d_in[9];
    float* out = (float*)d_out;

    const size_t qk_smem   = (size_t)HC * Vv * sizeof(float);
    const size_t attn_smem = (size_t)2 * HC * Vv * sizeof(float);

    cudaFuncSetAttribute((const void*)qk_kernel,
                         cudaFuncAttributeMaxDynamicSharedMemorySize, (int)qk_smem);
    cudaFuncSetAttribute((const void*)attn_kernel,
                         cudaFuncAttributeMaxDynamicSharedMemorySize, (int)attn_smem);
    cudaFuncSetAttribute((const void*)main_kernel,
                         cudaFuncAttributeMaxDynamicSharedMemorySize, SMEM_MAIN);

    qk_kernel<<<640, 256, qk_smem>>>(tf, Wq, bq, Wk, bk);
    attn_kernel<<<1, 256, attn_smem>>>();
    wo_prep<<<512, 256>>>(Wo);
    main_kernel<<<Nn * 256, NTHREADS, SMEM_MAIN>>>(feature, Wv, bv, bo, out);
}